// round 6
// baseline (speedup 1.0000x reference)
#include <cuda_runtime.h>
#include <math.h>

#define BB   8
#define NN   40000
#define DD   256
#define SS   128
#define HID  64
#define RPB  8          // rows per block in fused middle kernel
#define NACC 18         // accumulation blocks per batch
#define PTS  2240       // points per accum block (18*2240 = 40320 >= 40000)
#define GPB  37         // gather blocks per batch (37*1082 = 40034 >= 40000)
#define GPTS 1082

// ---------------- device scratch (no allocations allowed) ----------------
__device__ int       g_pcnt[BB * NACC * SS];         // per-block partial counts
__device__ long long g_psum[BB * NACC * 3 * SS];     // per-block partial sums (fixed point 2^32)
__device__ float     g_a4  [BB * SS * DD];           // final per-superpoint table (masked)

__device__ __forceinline__ float geluf(float x) { return x * normcdff(x); }

// ---------------- K1: segment accumulation -> per-block partials (no global atomics) ----------------
__global__ __launch_bounds__(256) void accum_kernel(const float* __restrict__ coords,
                                                    const int* __restrict__ labels) {
    __shared__ int       s_cnt[SS];
    __shared__ long long s_sum[SS * 3];
    int b = blockIdx.y;
    int j = blockIdx.x;
    int base = j * PTS;
    int tid = threadIdx.x;

    for (int i = tid; i < SS; i += 256) {
        s_cnt[i] = 0;
        s_sum[i * 3 + 0] = 0; s_sum[i * 3 + 1] = 0; s_sum[i * 3 + 2] = 0;
    }
    __syncthreads();

    const float SCALEF = 4294967296.0f; // 2^32 fixed point: deterministic, err ~2^-24 rel
    for (int i = tid; i < PTS; i += 256) {
        int n = base + i;
        if (n < NN) {
            long long pt = (long long)b * NN + n;
            int lab = labels[pt] & (SS - 1);
            const float* c = coords + pt * 3;
            float x = c[0], y = c[1], z = c[2];
            atomicAdd(&s_cnt[lab], 1);
            atomicAdd((unsigned long long*)&s_sum[lab * 3 + 0],
                      (unsigned long long)__float2ll_rn(x * SCALEF));
            atomicAdd((unsigned long long*)&s_sum[lab * 3 + 1],
                      (unsigned long long)__float2ll_rn(y * SCALEF));
            atomicAdd((unsigned long long*)&s_sum[lab * 3 + 2],
                      (unsigned long long)__float2ll_rn(z * SCALEF));
        }
    }
    __syncthreads();

    if (tid < SS) {
        g_pcnt[(b * NACC + j) * SS + tid] = s_cnt[tid];
        #pragma unroll
        for (int c = 0; c < 3; c++)
            g_psum[((b * NACC + j) * 3 + c) * SS + tid] = s_sum[tid * 3 + c];
    }
}

// ---------------- K2: fully fused middle (centers -> rel -> MLP -> LN -> a4) ----------------
// grid (SS/RPB = 16, BB), 256 threads. Thread owns 2 rows x 4 cols in GEMM stages.
__global__ __launch_bounds__(256) void middle_kernel(
    const float* __restrict__ W1, const float* __restrict__ b1,
    const float* __restrict__ W2, const float* __restrict__ b2,
    const float* __restrict__ W3, const float* __restrict__ b3,
    const float* __restrict__ lng, const float* __restrict__ lnb,
    const float* __restrict__ W4, const float* __restrict__ b4)
{
    int b   = blockIdx.y;
    int r0  = blockIdx.x * RPB;
    int tid = threadIdx.x;
    int lane = tid & 31, w = tid >> 5;

    __shared__ float cx[SS], cy[SS], cz[SS], vm[SS];
    __shared__ float relS[RPB][4];
    __shared__ float maskS[RPB];
    __shared__ float h1s[RPB][HID];
    __shared__ float h2s[RPB][DD];
    __shared__ float ys [RPB][DD];
    __shared__ float redA[4][2][2], redB[4][2][2];
    __shared__ float s_nv;

    // ---- reduce partials -> centers for ALL superpoints of this batch ----
    if (tid < SS) {
        long long sx = 0, sy = 0, sz = 0; int cnt = 0;
        #pragma unroll 6
        for (int j = 0; j < NACC; j++) {
            cnt += g_pcnt[(b * NACC + j) * SS + tid];
            sx  += g_psum[((b * NACC + j) * 3 + 0) * SS + tid];
            sy  += g_psum[((b * NACC + j) * 3 + 1) * SS + tid];
            sz  += g_psum[((b * NACC + j) * 3 + 2) * SS + tid];
        }
        float cf = (float)cnt;
        float dc = fmaxf(cf, 1.0f);
        const float INV = 1.0f / 4294967296.0f;
        cx[tid] = ((float)sx * INV) / dc;
        cy[tid] = ((float)sy * INV) / dc;
        cz[tid] = ((float)sz * INV) / dc;
        vm[tid] = (cf >= 2.0f) ? 1.0f : 0.0f;
    }
    __syncthreads();
    if (tid == 0) {
        float t = 0.f;
        #pragma unroll 8
        for (int i = 0; i < SS; i++) t += vm[i];
        s_nv = t;
    }
    __syncthreads();
    float nv    = s_nv;
    float denom = fmaxf(nv, 1.0f);

    // ---- rel features: warp w (0..7) handles row r0+w ----
    {
        int s = r0 + w;
        float xs = cx[s], ysv = cy[s], zs = cz[s];
        float msum = 0.f, mind = INFINITY, fcnt = 0.f;
        #pragma unroll
        for (int t = lane; t < SS; t += 32) {
            float dx = xs - cx[t], dy = ysv - cy[t], dz = zs - cz[t];
            float d2 = dx * dx + dy * dy + dz * dz;
            float dist = (d2 > 0.f) ? sqrtf(d2) : 0.f;
            float v = vm[t];
            msum += dist * v;
            if (v > 0.f) mind = fminf(mind, dist);
            fcnt += (zs > cz[t] ? 1.0f : 0.0f) * v;
        }
        #pragma unroll
        for (int o = 16; o > 0; o >>= 1) {
            msum += __shfl_xor_sync(0xffffffffu, msum, o);
            mind  = fminf(mind, __shfl_xor_sync(0xffffffffu, mind, o));
            fcnt += __shfl_xor_sync(0xffffffffu, fcnt, o);
        }
        if (lane == 0) {
            relS[w][0] = msum / denom;
            relS[w][1] = mind;
            relS[w][2] = zs;
            relS[w][3] = fcnt / denom;
            maskS[w]   = vm[s] * ((nv >= 2.0f) ? 1.0f : 0.0f);
        }
    }
    __syncthreads();

    // ---- h1 = gelu(rel @ W1 + b1): thread covers rows rr, rr+4 at col j ----
    {
        int rr = tid >> 6, j = tid & 63;
        #pragma unroll
        for (int rsel = 0; rsel < 2; rsel++) {
            int r = rr + rsel * 4;
            float a = b1[j]
                    + relS[r][0] * W1[0 * HID + j]
                    + relS[r][1] * W1[1 * HID + j]
                    + relS[r][2] * W1[2 * HID + j]
                    + relS[r][3] * W1[3 * HID + j];
            h1s[r][j] = geluf(a);
        }
    }
    __syncthreads();

    // GEMM thread mapping: cg = tid&63 -> cols c0=cg*4..+3 ; rg = tid>>6 -> rows 2rg, 2rg+1
    int cg  = tid & 63;
    int c0  = cg * 4;
    int rg  = tid >> 6;
    int lr0 = 2 * rg, lr1 = lr0 + 1;
    int wig = (tid >> 5) & 1;  // warp-within-rowgroup (cols [wig*128, wig*128+128))

    // ---- stage A: h2 = h1 @ W2 + b2 (K=64) ----
    {
        float a0[4] = {0,0,0,0}, a1[4] = {0,0,0,0};
        #pragma unroll 4
        for (int k = 0; k < HID; k += 4) {
            float4 x0 = *(const float4*)&h1s[lr0][k];
            float4 x1 = *(const float4*)&h1s[lr1][k];
            #pragma unroll
            for (int kk = 0; kk < 4; kk++) {
                float4 w4 = __ldg((const float4*)(W2 + (k + kk) * DD + c0));
                float xs0 = (&x0.x)[kk], xs1 = (&x1.x)[kk];
                a0[0] += xs0 * w4.x; a0[1] += xs0 * w4.y; a0[2] += xs0 * w4.z; a0[3] += xs0 * w4.w;
                a1[0] += xs1 * w4.x; a1[1] += xs1 * w4.y; a1[2] += xs1 * w4.z; a1[3] += xs1 * w4.w;
            }
        }
        float4 bv = __ldg((const float4*)(b2 + c0));
        *(float4*)&h2s[lr0][c0] = make_float4(a0[0]+bv.x, a0[1]+bv.y, a0[2]+bv.z, a0[3]+bv.w);
        *(float4*)&h2s[lr1][c0] = make_float4(a1[0]+bv.x, a1[1]+bv.y, a1[2]+bv.z, a1[3]+bv.w);
    }
    __syncthreads();

    // ---- stage B: a3 = h2 @ W3 + b3 (K=256) -> registers ----
    float v0[4], v1[4];
    {
        float a0[4] = {0,0,0,0}, a1[4] = {0,0,0,0};
        #pragma unroll 4
        for (int k = 0; k < DD; k += 4) {
            float4 x0 = *(const float4*)&h2s[lr0][k];
            float4 x1 = *(const float4*)&h2s[lr1][k];
            #pragma unroll
            for (int kk = 0; kk < 4; kk++) {
                float4 w4 = __ldg((const float4*)(W3 + (k + kk) * DD + c0));
                float xs0 = (&x0.x)[kk], xs1 = (&x1.x)[kk];
                a0[0] += xs0 * w4.x; a0[1] += xs0 * w4.y; a0[2] += xs0 * w4.z; a0[3] += xs0 * w4.w;
                a1[0] += xs1 * w4.x; a1[1] += xs1 * w4.y; a1[2] += xs1 * w4.z; a1[3] += xs1 * w4.w;
            }
        }
        float4 bv = __ldg((const float4*)(b3 + c0));
        v0[0]=a0[0]+bv.x; v0[1]=a0[1]+bv.y; v0[2]=a0[2]+bv.z; v0[3]=a0[3]+bv.w;
        v1[0]=a1[0]+bv.x; v1[1]=a1[1]+bv.y; v1[2]=a1[2]+bv.z; v1[3]=a1[3]+bv.w;
    }

    // ---- layernorm (rows lr0, lr1 over 256 cols) ----
    {
        float s0 = v0[0]+v0[1]+v0[2]+v0[3];
        float s1 = v1[0]+v1[1]+v1[2]+v1[3];
        #pragma unroll
        for (int o = 16; o > 0; o >>= 1) {
            s0 += __shfl_xor_sync(0xffffffffu, s0, o);
            s1 += __shfl_xor_sync(0xffffffffu, s1, o);
        }
        if (lane == 0) { redA[rg][wig][0] = s0; redA[rg][wig][1] = s1; }
    }
    __syncthreads();
    float m0 = (redA[rg][0][0] + redA[rg][1][0]) * (1.0f/DD);
    float m1 = (redA[rg][0][1] + redA[rg][1][1]) * (1.0f/DD);
    float d0[4], d1[4];
    #pragma unroll
    for (int i = 0; i < 4; i++) { d0[i] = v0[i] - m0; d1[i] = v1[i] - m1; }
    {
        float s0 = d0[0]*d0[0]+d0[1]*d0[1]+d0[2]*d0[2]+d0[3]*d0[3];
        float s1 = d1[0]*d1[0]+d1[1]*d1[1]+d1[2]*d1[2]+d1[3]*d1[3];
        #pragma unroll
        for (int o = 16; o > 0; o >>= 1) {
            s0 += __shfl_xor_sync(0xffffffffu, s0, o);
            s1 += __shfl_xor_sync(0xffffffffu, s1, o);
        }
        if (lane == 0) { redB[rg][wig][0] = s0; redB[rg][wig][1] = s1; }
    }
    __syncthreads();
    float q0 = (redB[rg][0][0] + redB[rg][1][0]) * (1.0f/DD);
    float q1 = (redB[rg][0][1] + redB[rg][1][1]) * (1.0f/DD);
    float is0 = rsqrtf(q0 + 1e-5f), is1 = rsqrtf(q1 + 1e-5f);
    {
        float4 g4 = __ldg((const float4*)(lng + c0));
        float4 bb4 = __ldg((const float4*)(lnb + c0));
        float y0[4], y1[4];
        #pragma unroll
        for (int i = 0; i < 4; i++) {
            float gi = (&g4.x)[i], bi = (&bb4.x)[i];
            y0[i] = geluf(d0[i] * is0 * gi + bi);
            y1[i] = geluf(d1[i] * is1 * gi + bi);
        }
        *(float4*)&ys[lr0][c0] = make_float4(y0[0], y0[1], y0[2], y0[3]);
        *(float4*)&ys[lr1][c0] = make_float4(y1[0], y1[1], y1[2], y1[3]);
    }
    __syncthreads();

    // ---- stage C: a4 = (y @ W4 + b4) * mask -> g_a4 ----
    {
        float a0[4] = {0,0,0,0}, a1[4] = {0,0,0,0};
        #pragma unroll 4
        for (int k = 0; k < DD; k += 4) {
            float4 x0 = *(const float4*)&ys[lr0][k];
            float4 x1 = *(const float4*)&ys[lr1][k];
            #pragma unroll
            for (int kk = 0; kk < 4; kk++) {
                float4 w4 = __ldg((const float4*)(W4 + (k + kk) * DD + c0));
                float xs0 = (&x0.x)[kk], xs1 = (&x1.x)[kk];
                a0[0] += xs0 * w4.x; a0[1] += xs0 * w4.y; a0[2] += xs0 * w4.z; a0[3] += xs0 * w4.w;
                a1[0] += xs1 * w4.x; a1[1] += xs1 * w4.y; a1[2] += xs1 * w4.z; a1[3] += xs1 * w4.w;
            }
        }
        float4 bv = __ldg((const float4*)(b4 + c0));
        float mk0 = maskS[lr0], mk1 = maskS[lr1];
        float* out0 = g_a4 + ((long long)b * SS + r0 + lr0) * DD + c0;
        float* out1 = g_a4 + ((long long)b * SS + r0 + lr1) * DD + c0;
        *(float4*)out0 = make_float4((a0[0]+bv.x)*mk0, (a0[1]+bv.y)*mk0,
                                     (a0[2]+bv.z)*mk0, (a0[3]+bv.w)*mk0);
        *(float4*)out1 = make_float4((a1[0]+bv.x)*mk1, (a1[1]+bv.y)*mk1,
                                     (a1[2]+bv.z)*mk1, (a1[3]+bv.w)*mk1);
    }
}

// ---------------- K3: gather epilogue, smem-resident table (HBM-write roofline) ----------------
__global__ __launch_bounds__(1024) void gather_kernel(const int* __restrict__ labels,
                                                      float4* __restrict__ out) {
    extern __shared__ float tbl[];    // 128KB: full per-batch table
    int b   = blockIdx.y;
    int tid = threadIdx.x;

    // load batch table into smem (coalesced float4)
    const float4* src = (const float4*)(g_a4 + (long long)b * SS * DD);
    float4* dst = (float4*)tbl;
    #pragma unroll
    for (int i = tid; i < SS * DD / 4; i += 1024) dst[i] = src[i];
    __syncthreads();

    int w    = tid >> 5, lane = tid & 31;
    int start = blockIdx.x * GPTS;
    int end   = min(start + GPTS, NN);
    const int* labp = labels + b * NN;
    for (int p = start + w; p < end; p += 32) {
        int lab = __ldg(labp + p) & (SS - 1);          // warp-broadcast load
        const float4* row = (const float4*)(tbl + lab * DD);
        float4 u0 = row[lane];
        float4 u1 = row[lane + 32];
        float4* o = out + ((long long)b * NN + p) * (DD / 4);
        __stcs(o + lane,      u0);
        __stcs(o + lane + 32, u1);
    }
}

// ---------------- launch ----------------
extern "C" void kernel_launch(void* const* d_in, const int* in_sizes, int n_in,
                              void* d_out, int out_size) {
    const float* coords = (const float*)d_in[0];
    // d_in[1] = features (unused), d_in[3] = num_superpoints (compile-time 128)
    const int*   labels = (const int*)d_in[2];
    const float* W1  = (const float*)d_in[4];
    const float* b1  = (const float*)d_in[5];
    const float* W2  = (const float*)d_in[6];
    const float* b2  = (const float*)d_in[7];
    const float* W3  = (const float*)d_in[8];
    const float* b3  = (const float*)d_in[9];
    const float* lng = (const float*)d_in[10];
    const float* lnb = (const float*)d_in[11];
    const float* W4  = (const float*)d_in[12];
    const float* b4  = (const float*)d_in[13];

    static bool attr_set = false;
    if (!attr_set) {   // idempotent function-attribute config (not a stream op)
        cudaFuncSetAttribute(gather_kernel,
                             cudaFuncAttributeMaxDynamicSharedMemorySize, SS * DD * 4);
        attr_set = true;
    }

    accum_kernel<<<dim3(NACC, BB), 256>>>(coords, labels);
    middle_kernel<<<dim3(SS / RPB, BB), 256>>>(W1, b1, W2, b2, W3, b3, lng, lnb, W4, b4);
    gather_kernel<<<dim3(GPB, BB), 1024, SS * DD * 4>>>(labels, (float4*)d_out);
}

// round 8
// speedup vs baseline: 1.6535x; 1.6535x over previous
#include <cuda_runtime.h>
#include <math.h>

#define BB   8
#define NN   40000
#define DD   256
#define SS   128
#define HID  64
#define RPB  4          // rows per block in fused middle kernel
#define NACC 36         // accumulation blocks per batch
#define PTS  1112       // points per accum block (36*1112 = 40032 >= 40000)

// ---------------- device scratch (no allocations allowed) ----------------
__device__ long long g_p1[BB * NACC * SS];   // packed (cnt, z) partials
__device__ long long g_p2[BB * NACC * SS];   // packed (x, y) partials
__device__ float     g_a4[BB * SS * DD];     // final per-superpoint table (masked)

__device__ __forceinline__ float geluf(float x) { return x * normcdff(x); }

// ---------------- K1: segment accumulation, 2 packed smem atomics per point ----------------
// Fixed point scale 2^17. A1 = cnt*2^32 + (z17 + 2^31); A2 = x17*2^32 + (y17 + 2^31).
__global__ __launch_bounds__(256) void accum_kernel(const float* __restrict__ coords,
                                                    const int* __restrict__ labels) {
    __shared__ unsigned long long s1[SS], s2[SS];
    int b = blockIdx.y;
    int j = blockIdx.x;
    int base = j * PTS;
    int tid = threadIdx.x;

    for (int i = tid; i < SS; i += 256) { s1[i] = 0ULL; s2[i] = 0ULL; }
    __syncthreads();

    const float SC = 131072.0f; // 2^17
    for (int i = tid; i < PTS; i += 256) {
        int n = base + i;
        if (n < NN) {
            long long pt = (long long)b * NN + n;
            int lab = labels[pt] & (SS - 1);
            const float* c = coords + pt * 3;
            long long x17 = __float2int_rn(c[0] * SC);
            long long y17 = __float2int_rn(c[1] * SC);
            long long z17 = __float2int_rn(c[2] * SC);
            unsigned long long a1 = (unsigned long long)((1LL << 32) + (1LL << 31) + z17);
            unsigned long long a2 = (unsigned long long)((x17 << 32) + (1LL << 31) + y17);
            atomicAdd(&s1[lab], a1);
            atomicAdd(&s2[lab], a2);
        }
    }
    __syncthreads();

    if (tid < SS) {
        g_p1[(b * NACC + j) * SS + tid] = (long long)s1[tid];
        g_p2[(b * NACC + j) * SS + tid] = (long long)s2[tid];
    }
}

// ---------------- K2: fully fused middle (centers -> rel -> MLP -> LN -> a4) ----------------
__global__ __launch_bounds__(256) void middle_kernel(
    const float* __restrict__ W1, const float* __restrict__ b1,
    const float* __restrict__ W2, const float* __restrict__ b2,
    const float* __restrict__ W3, const float* __restrict__ b3,
    const float* __restrict__ lng, const float* __restrict__ lnb,
    const float* __restrict__ W4, const float* __restrict__ b4)
{
    int b   = blockIdx.y;
    int r0  = blockIdx.x * RPB;
    int tid = threadIdx.x;
    int lane = tid & 31, w = tid >> 5;

    __shared__ float cx[SS], cy[SS], cz[SS], vm[SS];
    __shared__ float relS[RPB][4];
    __shared__ float maskS[RPB];
    __shared__ float h1s[RPB][HID];
    __shared__ float h2s[RPB][DD];
    __shared__ float ys [RPB][DD];
    __shared__ float red[8 * RPB];
    __shared__ float s_nv;

    // ---- reduce packed partials -> centers for ALL superpoints of this batch ----
    if (tid < SS) {
        long long v1 = 0, v2 = 0;
        #pragma unroll 6
        for (int j = 0; j < NACC; j++) {
            v1 += g_p1[(b * NACC + j) * SS + tid];
            v2 += g_p2[(b * NACC + j) * SS + tid];
        }
        const long long T31 = 3LL << 31;
        long long cnt = (v1 + (T31 >> 1)) / T31;        // V1 = cnt*3*2^31 + z_sum
        long long zs  = v1 - cnt * T31;
        long long u   = v2 - (cnt << 31);               // = x_sum*2^32 + y_sum
        int  ylow = (int)(unsigned int)(u & 0xFFFFFFFFULL);
        long long xs = (u - (long long)ylow) >> 32;

        float cf = (float)cnt;
        float dc = fmaxf(cf, 1.0f);
        const float INV = 1.0f / 131072.0f;
        cx[tid] = ((float)xs   * INV) / dc;
        cy[tid] = ((float)ylow * INV) / dc;
        cz[tid] = ((float)zs   * INV) / dc;
        vm[tid] = (cf >= 2.0f) ? 1.0f : 0.0f;
    }
    __syncthreads();
    if (tid == 0) {
        float t = 0.f;
        #pragma unroll 8
        for (int i = 0; i < SS; i++) t += vm[i];
        s_nv = t;
    }
    __syncthreads();
    float nv    = s_nv;
    float denom = fmaxf(nv, 1.0f);

    // ---- rel features: warp r (0..3) handles row r0+r ----
    if (w < RPB) {
        int s = r0 + w;
        float xs = cx[s], ysv = cy[s], zs = cz[s];
        float msum = 0.f, mind = INFINITY, fcnt = 0.f;
        #pragma unroll
        for (int t = lane; t < SS; t += 32) {
            float dx = xs - cx[t], dy = ysv - cy[t], dz = zs - cz[t];
            float d2 = dx * dx + dy * dy + dz * dz;
            float dist = (d2 > 0.f) ? sqrtf(d2) : 0.f;
            float v = vm[t];
            msum += dist * v;
            if (v > 0.f) mind = fminf(mind, dist);
            fcnt += (zs > cz[t] ? 1.0f : 0.0f) * v;
        }
        #pragma unroll
        for (int o = 16; o > 0; o >>= 1) {
            msum += __shfl_xor_sync(0xffffffffu, msum, o);
            mind  = fminf(mind, __shfl_xor_sync(0xffffffffu, mind, o));
            fcnt += __shfl_xor_sync(0xffffffffu, fcnt, o);
        }
        if (lane == 0) {
            relS[w][0] = msum / denom;
            relS[w][1] = mind;
            relS[w][2] = zs;
            relS[w][3] = fcnt / denom;
            maskS[w]   = vm[s] * ((nv >= 2.0f) ? 1.0f : 0.0f);
        }
    }
    __syncthreads();

    // ---- h1 = gelu(rel @ W1 + b1): tid -> (r = tid>>6, j = tid&63) ----
    {
        int r = tid >> 6, j = tid & 63;
        float a = b1[j]
                + relS[r][0] * W1[0 * HID + j]
                + relS[r][1] * W1[1 * HID + j]
                + relS[r][2] * W1[2 * HID + j]
                + relS[r][3] * W1[3 * HID + j];
        h1s[r][j] = geluf(a);
    }
    __syncthreads();

    int c = tid;  // output column, 0..255

    // ---- stage A: h2 = h1 @ W2 + b2  (K=64) ----
    {
        float a0 = 0.f, a1 = 0.f, a2 = 0.f, a3 = 0.f;
        #pragma unroll 8
        for (int k = 0; k < HID; k++) {
            float wv = __ldg(W2 + k * DD + c);
            a0 += h1s[0][k] * wv; a1 += h1s[1][k] * wv;
            a2 += h1s[2][k] * wv; a3 += h1s[3][k] * wv;
        }
        float bv = b2[c];
        h2s[0][c] = a0 + bv; h2s[1][c] = a1 + bv;
        h2s[2][c] = a2 + bv; h2s[3][c] = a3 + bv;
    }
    __syncthreads();

    // ---- stage B: a3 = h2 @ W3 + b3  (K=256) -> registers ----
    float v0, v1, v2, v3;
    {
        float a0 = 0.f, a1 = 0.f, a2 = 0.f, a3 = 0.f;
        #pragma unroll 8
        for (int k = 0; k < DD; k++) {
            float wv = __ldg(W3 + k * DD + c);
            a0 += h2s[0][k] * wv; a1 += h2s[1][k] * wv;
            a2 += h2s[2][k] * wv; a3 += h2s[3][k] * wv;
        }
        float bv = b3[c];
        v0 = a0 + bv; v1 = a1 + bv; v2 = a2 + bv; v3 = a3 + bv;
    }

    // ---- layernorm (per row over 256 cols) + gelu ----
    {
        float s0 = v0, s1 = v1, s2 = v2, s3 = v3;
        #pragma unroll
        for (int o = 16; o > 0; o >>= 1) {
            s0 += __shfl_xor_sync(0xffffffffu, s0, o);
            s1 += __shfl_xor_sync(0xffffffffu, s1, o);
            s2 += __shfl_xor_sync(0xffffffffu, s2, o);
            s3 += __shfl_xor_sync(0xffffffffu, s3, o);
        }
        if (lane == 0) { red[w*4+0]=s0; red[w*4+1]=s1; red[w*4+2]=s2; red[w*4+3]=s3; }
    }
    __syncthreads();
    float m0=0,m1=0,m2=0,m3=0;
    #pragma unroll
    for (int i = 0; i < 8; i++) { m0+=red[i*4+0]; m1+=red[i*4+1]; m2+=red[i*4+2]; m3+=red[i*4+3]; }
    m0 *= (1.0f/DD); m1 *= (1.0f/DD); m2 *= (1.0f/DD); m3 *= (1.0f/DD);
    __syncthreads();
    float d0 = v0-m0, d1 = v1-m1, d2 = v2-m2, d3 = v3-m3;
    {
        float s0 = d0*d0, s1 = d1*d1, s2 = d2*d2, s3 = d3*d3;
        #pragma unroll
        for (int o = 16; o > 0; o >>= 1) {
            s0 += __shfl_xor_sync(0xffffffffu, s0, o);
            s1 += __shfl_xor_sync(0xffffffffu, s1, o);
            s2 += __shfl_xor_sync(0xffffffffu, s2, o);
            s3 += __shfl_xor_sync(0xffffffffu, s3, o);
        }
        if (lane == 0) { red[w*4+0]=s0; red[w*4+1]=s1; red[w*4+2]=s2; red[w*4+3]=s3; }
    }
    __syncthreads();
    float q0=0,q1=0,q2=0,q3=0;
    #pragma unroll
    for (int i = 0; i < 8; i++) { q0+=red[i*4+0]; q1+=red[i*4+1]; q2+=red[i*4+2]; q3+=red[i*4+3]; }
    float g = lng[c], bb = lnb[c];
    ys[0][c] = geluf(d0 * rsqrtf(q0*(1.0f/DD) + 1e-5f) * g + bb);
    ys[1][c] = geluf(d1 * rsqrtf(q1*(1.0f/DD) + 1e-5f) * g + bb);
    ys[2][c] = geluf(d2 * rsqrtf(q2*(1.0f/DD) + 1e-5f) * g + bb);
    ys[3][c] = geluf(d3 * rsqrtf(q3*(1.0f/DD) + 1e-5f) * g + bb);
    __syncthreads();

    // ---- stage C: a4 = (y @ W4 + b4) * mask -> g_a4 ----
    {
        float a0 = 0.f, a1 = 0.f, a2 = 0.f, a3 = 0.f;
        #pragma unroll 8
        for (int k = 0; k < DD; k++) {
            float wv = __ldg(W4 + k * DD + c);
            a0 += ys[0][k] * wv; a1 += ys[1][k] * wv;
            a2 += ys[2][k] * wv; a3 += ys[3][k] * wv;
        }
        float bv = b4[c];
        float* out = g_a4 + ((long long)b * SS + r0) * DD + c;
        out[0 * DD] = (a0 + bv) * maskS[0];
        out[1 * DD] = (a1 + bv) * maskS[1];
        out[2 * DD] = (a2 + bv) * maskS[2];
        out[3 * DD] = (a3 + bv) * maskS[3];
    }
}

// ---------------- K3: gather epilogue (HBM-write-bound roofline) ----------------
// Each thread writes 2 float4s of one point's row; one label per warp (broadcast).
__global__ void gather_kernel(const int* __restrict__ labels, float4* __restrict__ out) {
    int b   = blockIdx.y;
    int idx = blockIdx.x * 256 + threadIdx.x;   // 0 .. NN*32-1 (exact, 5000 blocks)
    int pt  = idx >> 5;                         // point within batch
    int c4  = idx & 31;
    int lab = __ldg(labels + b * NN + pt) & (SS - 1);
    const float4* row = (const float4*)(g_a4 + (long long)(b * SS + lab) * DD);
    float4 u0 = __ldg(row + c4);
    float4 u1 = __ldg(row + c4 + 32);
    float4* o = out + ((long long)b * NN + pt) * (DD / 4);
    __stcs(o + c4,      u0);
    __stcs(o + c4 + 32, u1);
}

// ---------------- launch ----------------
extern "C" void kernel_launch(void* const* d_in, const int* in_sizes, int n_in,
                              void* d_out, int out_size) {
    const float* coords = (const float*)d_in[0];
    // d_in[1] = features (unused), d_in[3] = num_superpoints (compile-time 128)
    const int*   labels = (const int*)d_in[2];
    const float* W1  = (const float*)d_in[4];
    const float* b1  = (const float*)d_in[5];
    const float* W2  = (const float*)d_in[6];
    const float* b2  = (const float*)d_in[7];
    const float* W3  = (const float*)d_in[8];
    const float* b3  = (const float*)d_in[9];
    const float* lng = (const float*)d_in[10];
    const float* lnb = (const float*)d_in[11];
    const float* W4  = (const float*)d_in[12];
    const float* b4  = (const float*)d_in[13];

    accum_kernel<<<dim3(NACC, BB), 256>>>(coords, labels);
    middle_kernel<<<dim3(SS / RPB, BB), 256>>>(W1, b1, W2, b2, W3, b3, lng, lnb, W4, b4);
    gather_kernel<<<dim3((NN * 32) / 256, BB), 256>>>(labels, (float4*)d_out);
}

// round 13
// speedup vs baseline: 1.8297x; 1.1066x over previous
#include <cuda_runtime.h>
#include <math.h>

#define BB   8
#define NN   40000
#define DD   256
#define SS   128
#define HID  64
#define RPB  4          // rows per block in fused middle kernel
#define NACC 36         // accumulation blocks per batch
#define PTS  1112       // points per accum block (36*1112 = 40032 >= 40000)

// ---------------- device scratch (no allocations allowed) ----------------
__device__ long long g_p1[BB * NACC * SS];   // packed (cnt, z) partials
__device__ long long g_p2[BB * NACC * SS];   // packed (x, y) partials
__device__ float     g_a4[BB * SS * DD];     // final per-superpoint table (masked)

__device__ __forceinline__ float geluf(float x) { return x * normcdff(x); }

// ---------------- K1: segment accumulation, 2 packed smem atomics per point ----------------
// Fixed point scale 2^17. A1 = cnt*2^32 + (z17 + 2^31); A2 = x17*2^32 + (y17 + 2^31).
// 2-way replicated histograms (warp parity) to halve smem-atomic conflicts.
__global__ __launch_bounds__(256) void accum_kernel(const float* __restrict__ coords,
                                                    const int* __restrict__ labels) {
    __shared__ unsigned long long s1[2][SS], s2[2][SS];
    int b = blockIdx.y;
    int j = blockIdx.x;
    int base = j * PTS;
    int tid = threadIdx.x;
    int rep = (tid >> 5) & 1;

    for (int i = tid; i < 2 * SS; i += 256) {
        s1[0][0 * SS] = s1[0][0 * SS]; // no-op to keep compiler happy about 2D
        ((unsigned long long*)s1)[i] = 0ULL;
        ((unsigned long long*)s2)[i] = 0ULL;
    }
    __syncthreads();

    const float SC = 131072.0f; // 2^17
    for (int i = tid; i < PTS; i += 256) {
        int n = base + i;
        if (n < NN) {
            long long pt = (long long)b * NN + n;
            int lab = labels[pt] & (SS - 1);
            const float* c = coords + pt * 3;
            long long x17 = __float2int_rn(c[0] * SC);
            long long y17 = __float2int_rn(c[1] * SC);
            long long z17 = __float2int_rn(c[2] * SC);
            unsigned long long a1 = (unsigned long long)((1LL << 32) + (1LL << 31) + z17);
            unsigned long long a2 = (unsigned long long)((x17 << 32) + (1LL << 31) + y17);
            atomicAdd(&s1[rep][lab], a1);
            atomicAdd(&s2[rep][lab], a2);
        }
    }
    __syncthreads();

    if (tid < SS) {
        g_p1[(b * NACC + j) * SS + tid] = (long long)(s1[0][tid] + s1[1][tid]);
        g_p2[(b * NACC + j) * SS + tid] = (long long)(s2[0][tid] + s2[1][tid]);
    }
}

// ---------------- K2: fully fused middle (centers -> rel -> MLP -> LN -> a4) ----------------
__global__ __launch_bounds__(256) void middle_kernel(
    const float* __restrict__ W1, const float* __restrict__ b1,
    const float* __restrict__ W2, const float* __restrict__ b2,
    const float* __restrict__ W3, const float* __restrict__ b3,
    const float* __restrict__ lng, const float* __restrict__ lnb,
    const float* __restrict__ W4, const float* __restrict__ b4)
{
    int b   = blockIdx.y;
    int r0  = blockIdx.x * RPB;
    int tid = threadIdx.x;
    int lane = tid & 31, w = tid >> 5;

    __shared__ float cx[SS], cy[SS], cz[SS], vm[SS];
    __shared__ float relS[RPB][4];
    __shared__ float maskS[RPB];
    __shared__ __align__(16) float h1s[RPB][HID];
    __shared__ __align__(16) float h2s[RPB][DD];
    __shared__ __align__(16) float ys [RPB][DD];
    __shared__ float red[8 * RPB];
    __shared__ float s_nv;

    // ---- reduce packed partials -> centers for ALL superpoints of this batch ----
    if (tid < SS) {
        long long v1 = 0, v2 = 0;
        #pragma unroll 6
        for (int j = 0; j < NACC; j++) {
            v1 += g_p1[(b * NACC + j) * SS + tid];
            v2 += g_p2[(b * NACC + j) * SS + tid];
        }
        const long long T31 = 3LL << 31;
        long long cnt = (v1 + (T31 >> 1)) / T31;        // V1 = cnt*3*2^31 + z_sum
        long long zs  = v1 - cnt * T31;
        long long u   = v2 - (cnt << 31);               // = x_sum*2^32 + y_sum
        int  ylow = (int)(unsigned int)(u & 0xFFFFFFFFULL);
        long long xs = (u - (long long)ylow) >> 32;

        float cf = (float)cnt;
        float dc = fmaxf(cf, 1.0f);
        const float INV = 1.0f / 131072.0f;
        cx[tid] = ((float)xs   * INV) / dc;
        cy[tid] = ((float)ylow * INV) / dc;
        cz[tid] = ((float)zs   * INV) / dc;
        vm[tid] = (cf >= 2.0f) ? 1.0f : 0.0f;
    }
    __syncthreads();
    if (tid == 0) {
        float t = 0.f;
        #pragma unroll 8
        for (int i = 0; i < SS; i++) t += vm[i];
        s_nv = t;
    }
    __syncthreads();
    float nv    = s_nv;
    float denom = fmaxf(nv, 1.0f);

    // ---- rel features: warp r (0..3) handles row r0+r ----
    if (w < RPB) {
        int s = r0 + w;
        float xs = cx[s], ysv = cy[s], zs = cz[s];
        float msum = 0.f, mind = INFINITY, fcnt = 0.f;
        #pragma unroll
        for (int t = lane; t < SS; t += 32) {
            float dx = xs - cx[t], dy = ysv - cy[t], dz = zs - cz[t];
            float d2 = dx * dx + dy * dy + dz * dz;
            float dist = (d2 > 0.f) ? sqrtf(d2) : 0.f;
            float v = vm[t];
            msum += dist * v;
            if (v > 0.f) mind = fminf(mind, dist);
            fcnt += (zs > cz[t] ? 1.0f : 0.0f) * v;
        }
        #pragma unroll
        for (int o = 16; o > 0; o >>= 1) {
            msum += __shfl_xor_sync(0xffffffffu, msum, o);
            mind  = fminf(mind, __shfl_xor_sync(0xffffffffu, mind, o));
            fcnt += __shfl_xor_sync(0xffffffffu, fcnt, o);
        }
        if (lane == 0) {
            relS[w][0] = msum / denom;
            relS[w][1] = mind;
            relS[w][2] = zs;
            relS[w][3] = fcnt / denom;
            maskS[w]   = vm[s] * ((nv >= 2.0f) ? 1.0f : 0.0f);
        }
    }
    __syncthreads();

    // ---- h1 = gelu(rel @ W1 + b1): tid -> (r = tid>>6, j = tid&63) ----
    {
        int r = tid >> 6, j = tid & 63;
        float a = b1[j]
                + relS[r][0] * W1[0 * HID + j]
                + relS[r][1] * W1[1 * HID + j]
                + relS[r][2] * W1[2 * HID + j]
                + relS[r][3] * W1[3 * HID + j];
        h1s[r][j] = geluf(a);
    }
    __syncthreads();

    int c = tid;  // output column, 0..255

    // ---- stage A: h2 = h1 @ W2 + b2  (K=64), float4 LDS on x ----
    {
        float a0 = 0.f, a1 = 0.f, a2 = 0.f, a3 = 0.f;
        #pragma unroll
        for (int k = 0; k < HID; k += 4) {
            float4 x0 = *(const float4*)&h1s[0][k];
            float4 x1 = *(const float4*)&h1s[1][k];
            float4 x2 = *(const float4*)&h1s[2][k];
            float4 x3 = *(const float4*)&h1s[3][k];
            #pragma unroll
            for (int kk = 0; kk < 4; kk++) {
                float wv = __ldg(W2 + (k + kk) * DD + c);
                a0 += (&x0.x)[kk] * wv; a1 += (&x1.x)[kk] * wv;
                a2 += (&x2.x)[kk] * wv; a3 += (&x3.x)[kk] * wv;
            }
        }
        float bv = b2[c];
        h2s[0][c] = a0 + bv; h2s[1][c] = a1 + bv;
        h2s[2][c] = a2 + bv; h2s[3][c] = a3 + bv;
    }
    __syncthreads();

    // ---- stage B: a3 = h2 @ W3 + b3  (K=256) -> registers, float4 LDS on x ----
    float v0, v1, v2, v3;
    {
        float a0 = 0.f, a1 = 0.f, a2 = 0.f, a3 = 0.f;
        #pragma unroll 8
        for (int k = 0; k < DD; k += 4) {
            float4 x0 = *(const float4*)&h2s[0][k];
            float4 x1 = *(const float4*)&h2s[1][k];
            float4 x2 = *(const float4*)&h2s[2][k];
            float4 x3 = *(const float4*)&h2s[3][k];
            #pragma unroll
            for (int kk = 0; kk < 4; kk++) {
                float wv = __ldg(W3 + (k + kk) * DD + c);
                a0 += (&x0.x)[kk] * wv; a1 += (&x1.x)[kk] * wv;
                a2 += (&x2.x)[kk] * wv; a3 += (&x3.x)[kk] * wv;
            }
        }
        float bv = b3[c];
        v0 = a0 + bv; v1 = a1 + bv; v2 = a2 + bv; v3 = a3 + bv;
    }

    // ---- layernorm (per row over 256 cols) + gelu ----
    {
        float s0 = v0, s1 = v1, s2 = v2, s3 = v3;
        #pragma unroll
        for (int o = 16; o > 0; o >>= 1) {
            s0 += __shfl_xor_sync(0xffffffffu, s0, o);
            s1 += __shfl_xor_sync(0xffffffffu, s1, o);
            s2 += __shfl_xor_sync(0xffffffffu, s2, o);
            s3 += __shfl_xor_sync(0xffffffffu, s3, o);
        }
        if (lane == 0) { red[w*4+0]=s0; red[w*4+1]=s1; red[w*4+2]=s2; red[w*4+3]=s3; }
    }
    __syncthreads();
    float m0=0,m1=0,m2=0,m3=0;
    #pragma unroll
    for (int i = 0; i < 8; i++) { m0+=red[i*4+0]; m1+=red[i*4+1]; m2+=red[i*4+2]; m3+=red[i*4+3]; }
    m0 *= (1.0f/DD); m1 *= (1.0f/DD); m2 *= (1.0f/DD); m3 *= (1.0f/DD);
    __syncthreads();
    float d0 = v0-m0, d1 = v1-m1, d2 = v2-m2, d3 = v3-m3;
    {
        float s0 = d0*d0, s1 = d1*d1, s2 = d2*d2, s3 = d3*d3;
        #pragma unroll
        for (int o = 16; o > 0; o >>= 1) {
            s0 += __shfl_xor_sync(0xffffffffu, s0, o);
            s1 += __shfl_xor_sync(0xffffffffu, s1, o);
            s2 += __shfl_xor_sync(0xffffffffu, s2, o);
            s3 += __shfl_xor_sync(0xffffffffu, s3, o);
        }
        if (lane == 0) { red[w*4+0]=s0; red[w*4+1]=s1; red[w*4+2]=s2; red[w*4+3]=s3; }
    }
    __syncthreads();
    float q0=0,q1=0,q2=0,q3=0;
    #pragma unroll
    for (int i = 0; i < 8; i++) { q0+=red[i*4+0]; q1+=red[i*4+1]; q2+=red[i*4+2]; q3+=red[i*4+3]; }
    float g = lng[c], bb = lnb[c];
    ys[0][c] = geluf(d0 * rsqrtf(q0*(1.0f/DD) + 1e-5f) * g + bb);
    ys[1][c] = geluf(d1 * rsqrtf(q1*(1.0f/DD) + 1e-5f) * g + bb);
    ys[2][c] = geluf(d2 * rsqrtf(q2*(1.0f/DD) + 1e-5f) * g + bb);
    ys[3][c] = geluf(d3 * rsqrtf(q3*(1.0f/DD) + 1e-5f) * g + bb);
    __syncthreads();

    // ---- stage C: a4 = (y @ W4 + b4) * mask -> g_a4, float4 LDS on x ----
    {
        float a0 = 0.f, a1 = 0.f, a2 = 0.f, a3 = 0.f;
        #pragma unroll 8
        for (int k = 0; k < DD; k += 4) {
            float4 x0 = *(const float4*)&ys[0][k];
            float4 x1 = *(const float4*)&ys[1][k];
            float4 x2 = *(const float4*)&ys[2][k];
            float4 x3 = *(const float4*)&ys[3][k];
            #pragma unroll
            for (int kk = 0; kk < 4; kk++) {
                float wv = __ldg(W4 + (k + kk) * DD + c);
                a0 += (&x0.x)[kk] * wv; a1 += (&x1.x)[kk] * wv;
                a2 += (&x2.x)[kk] * wv; a3 += (&x3.x)[kk] * wv;
            }
        }
        float bv = b4[c];
        float* out = g_a4 + ((long long)b * SS + r0) * DD + c;
        out[0 * DD] = (a0 + bv) * maskS[0];
        out[1 * DD] = (a1 + bv) * maskS[1];
        out[2 * DD] = (a2 + bv) * maskS[2];
        out[3 * DD] = (a3 + bv) * maskS[3];
    }
}

// ---------------- K3: gather epilogue (HBM-write-bound roofline) ----------------
// Each thread writes 2 float4s of one point's row; one label per warp (broadcast).
__global__ void gather_kernel(const int* __restrict__ labels, float4* __restrict__ out) {
    int b   = blockIdx.y;
    int idx = blockIdx.x * 256 + threadIdx.x;   // 0 .. NN*32-1 (exact, 5000 blocks)
    int pt  = idx >> 5;                         // point within batch
    int c4  = idx & 31;
    int lab = __ldg(labels + b * NN + pt) & (SS - 1);
    const float4* row = (const float4*)(g_a4 + (long long)(b * SS + lab) * DD);
    float4 u0 = __ldg(row + c4);
    float4 u1 = __ldg(row + c4 + 32);
    float4* o = out + ((long long)b * NN + pt) * (DD / 4);
    __stcs(o + c4,      u0);
    __stcs(o + c4 + 32, u1);
}

// ---------------- launch ----------------
extern "C" void kernel_launch(void* const* d_in, const int* in_sizes, int n_in,
                              void* d_out, int out_size) {
    const float* coords = (const float*)d_in[0];
    // d_in[1] = features (unused), d_in[3] = num_superpoints (compile-time 128)
    const int*   labels = (const int*)d_in[2];
    const float* W1  = (const float*)d_in[4];
    const float* b1  = (const float*)d_in[5];
    const float* W2  = (const float*)d_in[6];
    const float* b2  = (const float*)d_in[7];
    const float* W3  = (const float*)d_in[8];
    const float* b3  = (const float*)d_in[9];
    const float* lng = (const float*)d_in[10];
    const float* lnb = (const float*)d_in[11];
    const float* W4  = (const float*)d_in[12];
    const float* b4  = (const float*)d_in[13];

    accum_kernel<<<dim3(NACC, BB), 256>>>(coords, labels);
    middle_kernel<<<dim3(SS / RPB, BB), 256>>>(W1, b1, W2, b2, W3, b3, lng, lnb, W4, b4);
    gather_kernel<<<dim3((NN * 32) / 256, BB), 256>>>(labels, (float4*)d_out);
}